// round 12
// baseline (speedup 1.0000x reference)
#include <cuda_runtime.h>

// FeatureInteraction: B=16384, F=27, D=128
// out[b] = concat(embeddings[b].flatten() (3456), triu(E E^T, k=1) (351)) -> 3807 floats
//
// R12: persistent blocks. 128 thr = 2 independent warp-pairs; each pair
//      grid-strides over batch elements (~8 iters). Per iteration: R8-style
//      scalar deep-MLP staging (27 LDG in flight, STS swizzled + flat STG
//      direct from registers), XOR-swizzled LDS.128 + fma.rn.f32x2 compute,
//      pair-local named-barrier reduction. 28 warps/SM via 65-reg budget.

static constexpr int F      = 27;
static constexpr int F_PAD  = 28;
static constexpr int D      = 128;
static constexpr int HALF   = 64;
static constexpr int FLAT   = F * D;              // 3456
static constexpr int NPAIR  = (F * (F - 1)) / 2;  // 351
static constexpr int ROWLEN = FLAT + NPAIR;       // 3807
static constexpr int SLOT   = F_PAD * D;          // 3584 words per batch tile
static constexpr int THREADS = 128;               // 2 pairs
static constexpr int GRID   = 1036;               // 148 SMs x 7 blocks

__device__ __forceinline__ unsigned long long pack2(float x, float y) {
    unsigned long long r;
    asm("mov.b64 %0, {%1, %2};" : "=l"(r) : "f"(x), "f"(y));
    return r;
}
__device__ __forceinline__ void unpack2(unsigned long long v, float& x, float& y) {
    asm("mov.b64 {%0, %1}, %2;" : "=f"(x), "=f"(y) : "l"(v));
}
__device__ __forceinline__ void ffma2(unsigned long long& acc,
                                      unsigned long long a, unsigned long long b) {
    asm("fma.rn.f32x2 %0, %1, %2, %0;" : "+l"(acc) : "l"(a), "l"(b));
}

// Row f = words [f*128, f*128+128); 16B chunk c stored at slot c ^ (f>>2).
// f>>2 <= 6 < 8 keeps the XOR within each 8-chunk octet, so columns [0,64)
// and [64,128) are closed under the swizzle (d-half regions don't mix).
__device__ __forceinline__ int sm_word(int f, int d) {
    return f * D + ((((d >> 2) ^ (f >> 2)) << 2) | (d & 3));
}

__global__ void __launch_bounds__(THREADS, 7)
fi_kernel(const float* __restrict__ in, float* __restrict__ out, int batch)
{
    __shared__ float sm[2 * SLOT];                // 28672 B (one slot per pair)

    const int tid  = threadIdx.x;
    const int pair = tid >> 6;                    // 0,1: independent pairs
    const int dh   = (tid >> 5) & 1;              // d-half owned by this warp
    const int lane = tid & 31;
    float* smb = sm + pair * SLOT;

    // lane -> 4x4 tile coords of the 7x7 tile grid over the triangle
    int ti = 0, tj = 0;
    if (lane < 28) {
        int l = lane, cnt = 7;
        while (l >= cnt) { l -= cnt; ++ti; --cnt; }
        tj = ti + l;
    }

    const int d0 = dh * HALF + lane;              // this lane's two columns
    const long stride = 2L * GRID;

    for (long b = (long)blockIdx.x * 2 + pair; b < batch; b += stride) {
        const float* __restrict__ inb  = in  + (size_t)b * FLAT;
        float*       __restrict__ outb = out + (size_t)b * ROWLEN;

        // ---- Stage this warp's d-half: 2 rounds of 27 batched LDGs; flat
        // output stored straight from registers (no smem round trip).
        smb[sm_word(27, d0)]      = 0.f;          // zero pad-row half
        smb[sm_word(27, d0 + 32)] = 0.f;
        {
            float v[F];
            #pragma unroll
            for (int f = 0; f < F; ++f) v[f] = inb[f * D + d0];
            #pragma unroll
            for (int f = 0; f < F; ++f) {
                smb[sm_word(f, d0)] = v[f];
                outb[f * D + d0]    = v[f];
            }
            #pragma unroll
            for (int f = 0; f < F; ++f) v[f] = inb[f * D + d0 + 32];
            #pragma unroll
            for (int f = 0; f < F; ++f) {
                smb[sm_word(f, d0 + 32)] = v[f];
                outb[f * D + d0 + 32]    = v[f];
            }
        }
        __syncwarp();

        // ---- Partial gram over this warp's chunks [16dh, 16dh+16) ----
        float val[4][4];
        if (lane < 28) {
            unsigned long long acc[4][4];
            #pragma unroll
            for (int r = 0; r < 4; ++r)
                #pragma unroll
                for (int c = 0; c < 4; ++c) acc[r][c] = 0ull;

            const float* pi = smb + (4 * ti) * D;
            const float* pj = smb + (4 * tj) * D;

            const int c0 = dh * 16;
            #pragma unroll 2
            for (int c = c0; c < c0 + 16; ++c) {
                const int ci = (c ^ ti) << 2;
                const int cj = (c ^ tj) << 2;
                float4 ai4[4], aj4[4];
                #pragma unroll
                for (int r = 0; r < 4; ++r)
                    ai4[r] = *reinterpret_cast<const float4*>(pi + r * D + ci);
                #pragma unroll
                for (int cc = 0; cc < 4; ++cc)
                    aj4[cc] = *reinterpret_cast<const float4*>(pj + cc * D + cj);

                unsigned long long ailo[4], aihi[4], ajlo[4], ajhi[4];
                #pragma unroll
                for (int r = 0; r < 4; ++r) {
                    ailo[r] = pack2(ai4[r].x, ai4[r].y);
                    aihi[r] = pack2(ai4[r].z, ai4[r].w);
                }
                #pragma unroll
                for (int cc = 0; cc < 4; ++cc) {
                    ajlo[cc] = pack2(aj4[cc].x, aj4[cc].y);
                    ajhi[cc] = pack2(aj4[cc].z, aj4[cc].w);
                }
                #pragma unroll
                for (int r = 0; r < 4; ++r)
                    #pragma unroll
                    for (int cc = 0; cc < 4; ++cc) {
                        ffma2(acc[r][cc], ailo[r], ajlo[cc]);
                        ffma2(acc[r][cc], aihi[r], ajhi[cc]);
                    }
            }
            #pragma unroll
            for (int r = 0; r < 4; ++r)
                #pragma unroll
                for (int cc = 0; cc < 4; ++cc) {
                    float lo, hi;
                    unpack2(acc[r][cc], lo, hi);
                    val[r][cc] = lo + hi;
                }
        }
        __syncwarp();   // this warp's reads of smb done; its columns = scratch

        // ---- dh==1 deposits 448 partials into its own (dead) columns ----
        if (lane < 28 && dh == 1) {
            #pragma unroll
            for (int v = 0; v < 16; ++v) {
                const int w = v * 28 + lane;
                smb[(w >> 6) * D + HALF + (w & 63)] = val[v >> 2][v & 3];
            }
        }
        // bar A: deposits visible to dh0 (pair-scope named barrier)
        asm volatile("bar.sync %0, 64;" :: "r"(1 + pair) : "memory");

        // ---- dh==0 reduces + scatters triu into its own (dead) columns ----
        if (lane < 28 && dh == 0) {
            #pragma unroll
            for (int v = 0; v < 16; ++v) {
                const int w = v * 28 + lane;
                const float s = val[v >> 2][v & 3]
                              + smb[(w >> 6) * D + HALF + (w & 63)];
                const int r = v >> 2, cc = v & 3;
                const int ii = 4 * ti + r, jj = 4 * tj + cc;
                if (ii < jj && jj < F) {
                    const int off = ii * F - (ii * (ii + 1)) / 2 + (jj - ii - 1);
                    smb[(off >> 6) * D + (off & 63)] = s;
                }
            }
        }
        // bar B: deposits consumed -> dh1 may restage its columns next iter;
        // dh0's triu scratch is only touched by dh0 (warp-ordered vs its STG).
        asm volatile("bar.sync %0, 64;" :: "r"(1 + pair) : "memory");

        // ---- dh==0 stores the 351 triu floats coalesced ----
        if (dh == 0) {
            float* outp = outb + FLAT;
            #pragma unroll
            for (int it = 0; it < (NPAIR + 31) / 32; ++it) {
                const int x = it * 32 + lane;
                if (x < NPAIR) outp[x] = smb[(x >> 6) * D + (x & 63)];
            }
        }
    }
}

extern "C" void kernel_launch(void* const* d_in, const int* in_sizes, int n_in,
                              void* d_out, int out_size)
{
    const float* in = (const float*)d_in[0];
    float* out = (float*)d_out;
    const int batch = in_sizes[0] / FLAT;      // 16384
    fi_kernel<<<GRID, THREADS>>>(in, out, batch);
}

// round 13
// speedup vs baseline: 1.2038x; 1.2038x over previous
#include <cuda_runtime.h>

// FeatureInteraction: B=16384, F=27, D=128
// out[b] = concat(embeddings[b].flatten() (3456), triu(E E^T, k=1) (351)) -> 3807 floats
//
// R13: NBATCH=2 (128 thr = 2 independent warp-pairs, one batch element each),
//      grid 8192 (oversubscribed short blocks — no persistence). R8-style
//      staging: 27-deep batched LDG.32, swizzled STS, flat output STG direct
//      from registers. Compute: XOR-swizzled LDS.128 + fma.rn.f32x2, d-half
//      per warp; pair-scope named-barrier reduction. 28 warps/SM (72 regs).

static constexpr int F      = 27;
static constexpr int F_PAD  = 28;
static constexpr int D      = 128;
static constexpr int HALF   = 64;
static constexpr int FLAT   = F * D;              // 3456
static constexpr int NPAIR  = (F * (F - 1)) / 2;  // 351
static constexpr int ROWLEN = FLAT + NPAIR;       // 3807
static constexpr int SLOT   = F_PAD * D;          // 3584 words per batch tile
static constexpr int NBATCH = 2;                  // batch elements per block
static constexpr int THREADS = 128;

__device__ __forceinline__ unsigned long long pack2(float x, float y) {
    unsigned long long r;
    asm("mov.b64 %0, {%1, %2};" : "=l"(r) : "f"(x), "f"(y));
    return r;
}
__device__ __forceinline__ void unpack2(unsigned long long v, float& x, float& y) {
    asm("mov.b64 {%0, %1}, %2;" : "=f"(x), "=f"(y) : "l"(v));
}
__device__ __forceinline__ void ffma2(unsigned long long& acc,
                                      unsigned long long a, unsigned long long b) {
    asm("fma.rn.f32x2 %0, %1, %2, %0;" : "+l"(acc) : "l"(a), "l"(b));
}

// Row f = words [f*128, f*128+128); 16B chunk c stored at slot c ^ (f>>2).
// f>>2 <= 6 < 8 keeps the XOR within each 8-chunk octet, so the d-half
// regions [0,64) / [64,128) are closed under the swizzle.
__device__ __forceinline__ int sm_word(int f, int d) {
    return f * D + ((((d >> 2) ^ (f >> 2)) << 2) | (d & 3));
}

__global__ void __launch_bounds__(THREADS, 7)
fi_kernel(const float* __restrict__ in, float* __restrict__ out, int batch)
{
    __shared__ float sm[NBATCH * SLOT];           // 28672 B (one slot per pair)

    const int tid  = threadIdx.x;
    const int pair = tid >> 6;                    // 0,1: independent pairs
    const int dh   = (tid >> 5) & 1;              // d-half owned by this warp
    const int lane = tid & 31;
    const long b   = (long)blockIdx.x * NBATCH + pair;
    if (b >= batch) return;                       // whole pair exits together

    float* smb = sm + pair * SLOT;
    const float* __restrict__ inb  = in  + (size_t)b * FLAT;
    float*       __restrict__ outb = out + (size_t)b * ROWLEN;

    // lane -> 4x4 tile coords of the 7x7 tile grid over the triangle
    int ti = 0, tj = 0;
    if (lane < 28) {
        int l = lane, cnt = 7;
        while (l >= cnt) { l -= cnt; ++ti; --cnt; }
        tj = ti + l;
    }

    const int d0 = dh * HALF + lane;              // this lane's two columns

    // ---- Stage this warp's d-half: 2 rounds of 27 batched LDGs; flat
    // output stored straight from registers (no smem round trip).
    smb[sm_word(27, d0)]      = 0.f;              // zero pad-row half
    smb[sm_word(27, d0 + 32)] = 0.f;
    {
        float v[F];
        #pragma unroll
        for (int f = 0; f < F; ++f) v[f] = inb[f * D + d0];
        #pragma unroll
        for (int f = 0; f < F; ++f) {
            smb[sm_word(f, d0)] = v[f];
            outb[f * D + d0]    = v[f];
        }
        #pragma unroll
        for (int f = 0; f < F; ++f) v[f] = inb[f * D + d0 + 32];
        #pragma unroll
        for (int f = 0; f < F; ++f) {
            smb[sm_word(f, d0 + 32)] = v[f];
            outb[f * D + d0 + 32]    = v[f];
        }
    }
    __syncwarp();

    // ---- Partial gram over this warp's chunks [16dh, 16dh+16) ----
    float val[4][4];
    if (lane < 28) {
        unsigned long long acc[4][4];
        #pragma unroll
        for (int r = 0; r < 4; ++r)
            #pragma unroll
            for (int c = 0; c < 4; ++c) acc[r][c] = 0ull;

        const float* pi = smb + (4 * ti) * D;
        const float* pj = smb + (4 * tj) * D;

        const int c0 = dh * 16;
        #pragma unroll 2
        for (int c = c0; c < c0 + 16; ++c) {
            const int ci = (c ^ ti) << 2;
            const int cj = (c ^ tj) << 2;
            float4 ai4[4], aj4[4];
            #pragma unroll
            for (int r = 0; r < 4; ++r)
                ai4[r] = *reinterpret_cast<const float4*>(pi + r * D + ci);
            #pragma unroll
            for (int cc = 0; cc < 4; ++cc)
                aj4[cc] = *reinterpret_cast<const float4*>(pj + cc * D + cj);

            unsigned long long ailo[4], aihi[4], ajlo[4], ajhi[4];
            #pragma unroll
            for (int r = 0; r < 4; ++r) {
                ailo[r] = pack2(ai4[r].x, ai4[r].y);
                aihi[r] = pack2(ai4[r].z, ai4[r].w);
            }
            #pragma unroll
            for (int cc = 0; cc < 4; ++cc) {
                ajlo[cc] = pack2(aj4[cc].x, aj4[cc].y);
                ajhi[cc] = pack2(aj4[cc].z, aj4[cc].w);
            }
            #pragma unroll
            for (int r = 0; r < 4; ++r)
                #pragma unroll
                for (int cc = 0; cc < 4; ++cc) {
                    ffma2(acc[r][cc], ailo[r], ajlo[cc]);
                    ffma2(acc[r][cc], aihi[r], ajhi[cc]);
                }
        }
        #pragma unroll
        for (int r = 0; r < 4; ++r)
            #pragma unroll
            for (int cc = 0; cc < 4; ++cc) {
                float lo, hi;
                unpack2(acc[r][cc], lo, hi);
                val[r][cc] = lo + hi;
            }
    }
    __syncwarp();   // this warp's reads of smb done; its columns = scratch

    // ---- dh==1 deposits 448 partials into its own (dead) columns ----
    if (lane < 28 && dh == 1) {
        #pragma unroll
        for (int v = 0; v < 16; ++v) {
            const int w = v * 28 + lane;
            smb[(w >> 6) * D + HALF + (w & 63)] = val[v >> 2][v & 3];
        }
    }
    // bar A: deposits visible to dh0 (pair-scope named barrier)
    asm volatile("bar.sync %0, 64;" :: "r"(1 + pair) : "memory");

    // ---- dh==0 reduces + scatters triu into its own (dead) columns ----
    if (lane < 28 && dh == 0) {
        #pragma unroll
        for (int v = 0; v < 16; ++v) {
            const int w = v * 28 + lane;
            const float s = val[v >> 2][v & 3]
                          + smb[(w >> 6) * D + HALF + (w & 63)];
            const int r = v >> 2, cc = v & 3;
            const int ii = 4 * ti + r, jj = 4 * tj + cc;
            if (ii < jj && jj < F) {
                const int off = ii * F - (ii * (ii + 1)) / 2 + (jj - ii - 1);
                smb[(off >> 6) * D + (off & 63)] = s;
            }
        }
    }
    __syncwarp();

    // ---- dh==0 stores the 351 triu floats coalesced ----
    if (dh == 0) {
        float* outp = outb + FLAT;
        #pragma unroll
        for (int it = 0; it < (NPAIR + 31) / 32; ++it) {
            const int x = it * 32 + lane;
            if (x < NPAIR) outp[x] = smb[(x >> 6) * D + (x & 63)];
        }
    }
}

extern "C" void kernel_launch(void* const* d_in, const int* in_sizes, int n_in,
                              void* d_out, int out_size)
{
    const float* in = (const float*)d_in[0];
    float* out = (float*)d_out;
    const int batch = in_sizes[0] / FLAT;            // 16384
    const int grid = (batch + NBATCH - 1) / NBATCH;  // 8192
    fi_kernel<<<grid, THREADS>>>(in, out, batch);
}